// round 7
// baseline (speedup 1.0000x reference)
#include <cuda_runtime.h>

#define NN 8192
#define INDIM 512
#define HID 50
#define ZD 128
#define NCAT 64
#define EPSV 1e-8f
#define NWORK_MAX (NN/32 + NCAT)

typedef unsigned long long u64;

// ---------------- scratch (device globals; no allocation allowed) ----------
__device__ float g_fxs[NN*ZD];   // fx in sorted order
__device__ float g_fzs[NN*ZD];   // fz in sorted order
__device__ float g_us [NN*ZD];   // u  in sorted order
__device__ float g_T  [NN];      // T  in sorted order
__device__ int   g_cnt[NCAT], g_start[NCAT];
__device__ int   g_sorted[NN];   // sorted pos -> original idx
__device__ int   g_pos[NN];      // original idx -> sorted pos
__device__ int   g_work[NWORK_MAX];
__device__ int   g_nwork;

// ---------------- f32x2 helpers ---------------------------------------------
__device__ __forceinline__ u64 dup2(float x){
    u64 r; asm("mov.b64 %0, {%1, %1};" : "=l"(r) : "f"(x)); return r;
}
__device__ __forceinline__ void fma2(u64 &d, u64 a, u64 b){
    asm("fma.rn.f32x2 %0, %1, %2, %0;" : "+l"(d) : "l"(a), "l"(b));
}
__device__ __forceinline__ float2 unpk(u64 v){
    float2 f; asm("mov.b64 {%0, %1}, %2;" : "=f"(f.x), "=f"(f.y) : "l"(v)); return f;
}

__device__ __forceinline__ float softplusf(float v){
    // __expf: ~2ulp RELATIVE error (safe); log1pf accurate for tiny args.
    return fmaxf(v, 0.f) + log1pf(__expf(-fabsf(v)));
}

// ---------------- fused bucket sort (single block) --------------------------
__global__ void bucket_kernel(const int* __restrict__ c){
    __shared__ int s_cnt[NCAT];
    __shared__ int s_cursor[NCAT];
    __shared__ int s_cat[NN];
    int tid = threadIdx.x;

    if (tid < NCAT) s_cnt[tid] = 0;
    __syncthreads();

    for (int i = tid; i < NN; i += 1024){
        int cc = c[i];
        cc = min(max(cc, 0), NCAT - 1);
        s_cat[i] = cc;
        atomicAdd(&s_cnt[cc], 1);
    }
    __syncthreads();

    if (tid == 0){
        int s = 0, w = 0;
        for (int cc = 0; cc < NCAT; cc++){
            s_cursor[cc] = s;
            g_start[cc]  = s;
            int n = s_cnt[cc];
            g_cnt[cc] = n;
            s += n;
            int nt = (n + 31) >> 5;
            for (int t = 0; t < nt; t++) g_work[w++] = (cc << 16) | t;
        }
        g_nwork = w;
    }
    __syncthreads();

    for (int i = tid; i < NN; i += 1024){
        int p = atomicAdd(&s_cursor[s_cat[i]], 1);
        g_sorted[p] = i;
        g_pos[i]    = p;
    }
}

// ---------------- fx = relu(x@W1+b1)@W2+b2  (32 rows / block) --------------
__global__ void fx_kernel(const float* __restrict__ x,  const float* __restrict__ W1,
                          const float* __restrict__ b1, const float* __restrict__ W2,
                          const float* __restrict__ b2){
    __shared__ __align__(16) float sbuf[8032];
    __shared__ float b1s[64];
    __shared__ float b2s[128];
    __shared__ int   posS[32];
    float (*As)[33]   = (float(*)[33])  sbuf;               // 32x33 = 1056
    float (*Bs)[64]   = (float(*)[64])  (sbuf + 1056);      // 32x64 = 2048 (16B-aligned: 1056*4=4224)
    float (*Hs)[51]   = (float(*)[51])  sbuf;               // 32x51 = 1632 (overlaps dead As/Bs)
    float (*W2s)[128] = (float(*)[128]) (sbuf + 1632);      // 50x128 = 6400

    int tid  = threadIdx.x;
    int row0 = blockIdx.x * 32;
    if (tid < 64)  b1s[tid] = (tid < HID) ? b1[tid] : 0.f;
    if (tid < 128) b2s[tid] = b2[tid];
    if (tid < 32)  posS[tid] = g_pos[row0 + tid];

    int rg = (tid >> 4) * 2;     // 0..30
    int cg = (tid & 15) * 4;     // 0..60
    u64 acc2[2][2] = {};         // [row][colpair]

    for (int k0 = 0; k0 < INDIM; k0 += 32){
        __syncthreads();                         // Bs reuse safe
        for (int e = tid; e < 32*32; e += 256){
            int r = e >> 5, k = e & 31;
            As[r][k] = x[(row0 + r)*INDIM + k0 + k];
        }
        for (int e = tid; e < 32*64; e += 256){
            int k = e >> 6, j = e & 63;
            Bs[k][j] = (j < HID) ? W1[(k0 + k)*HID + j] : 0.f;
        }
        __syncthreads();
        #pragma unroll
        for (int k = 0; k < 32; k++){
            u64 da0 = dup2(As[rg][k]);
            u64 da1 = dup2(As[rg+1][k]);
            ulonglong2 bb = *(const ulonglong2*)&Bs[k][cg];
            fma2(acc2[0][0], da0, bb.x); fma2(acc2[0][1], da0, bb.y);
            fma2(acc2[1][0], da1, bb.x); fma2(acc2[1][1], da1, bb.y);
        }
    }
    __syncthreads();

    // hidden (ReLU) into Hs
    #pragma unroll
    for (int i = 0; i < 2; i++){
        float2 p0 = unpk(acc2[i][0]);
        float2 p1 = unpk(acc2[i][1]);
        float hv[4] = {p0.x, p0.y, p1.x, p1.y};
        #pragma unroll
        for (int j = 0; j < 4; j++){
            int cc = cg + j;
            if (cc < HID) Hs[rg+i][cc] = fmaxf(hv[j] + b1s[cc], 0.f);
        }
    }
    for (int e = tid; e < HID*128; e += 256) W2s[e >> 7][e & 127] = W2[e];
    __syncthreads();

    for (int e = tid; e < 32*128; e += 256){
        int r = e >> 7, cc = e & 127;
        float v = b2s[cc];
        #pragma unroll
        for (int k = 0; k < HID; k++) v += Hs[r][k]*W2s[k][cc];
        g_fxs[(size_t)posS[r]*ZD + cc] = v;      // write in sorted order
    }
}

// ---------------- fz = z@Wz+bz  (32 rows / block) --------------------------
__global__ void fz_kernel(const float* __restrict__ z, const float* __restrict__ Wz,
                          const float* __restrict__ bz){
    __shared__ __align__(16) float Zs[32][33];
    __shared__ __align__(16) float Wzt[32*132];
    __shared__ float bzs[128];
    __shared__ int   posS[32];
    int tid  = threadIdx.x;
    int row0 = blockIdx.x * 32;
    if (tid < 128) bzs[tid] = bz[tid];
    if (tid < 32)  posS[tid] = g_pos[row0 + tid];

    int rg = (tid >> 4) * 2;     // 0..30
    int cg = (tid & 15) * 8;     // 0..120
    u64 acc2[2][4] = {};         // [row][colpair]

    for (int kt = 0; kt < ZD; kt += 32){
        __syncthreads();
        for (int e = tid; e < 32*32; e += 256){
            int r = e >> 5, k = e & 31;
            Zs[r][k] = z[(row0 + r)*ZD + kt + k];
        }
        for (int e = tid; e < 32*128; e += 256){
            int k = e >> 7, cc = e & 127;
            Wzt[k*132 + cc] = Wz[(kt + k)*ZD + cc];
        }
        __syncthreads();
        #pragma unroll
        for (int k = 0; k < 32; k++){
            u64 da0 = dup2(Zs[rg][k]);
            u64 da1 = dup2(Zs[rg+1][k]);
            ulonglong2 b0 = *(const ulonglong2*)&Wzt[k*132 + cg];
            ulonglong2 b1v = *(const ulonglong2*)&Wzt[k*132 + cg + 4];
            fma2(acc2[0][0], da0, b0.x); fma2(acc2[0][1], da0, b0.y);
            fma2(acc2[0][2], da0, b1v.x); fma2(acc2[0][3], da0, b1v.y);
            fma2(acc2[1][0], da1, b0.x); fma2(acc2[1][1], da1, b0.y);
            fma2(acc2[1][2], da1, b1v.x); fma2(acc2[1][3], da1, b1v.y);
        }
    }

    #pragma unroll
    for (int i = 0; i < 2; i++){
        size_t base = (size_t)posS[rg+i]*ZD + cg;
        float2 p0 = unpk(acc2[i][0]), p1 = unpk(acc2[i][1]);
        float2 p2 = unpk(acc2[i][2]), p3 = unpk(acc2[i][3]);
        float4 v0 = make_float4(p0.x + bzs[cg],   p0.y + bzs[cg+1],
                                p1.x + bzs[cg+2], p1.y + bzs[cg+3]);
        float4 v1 = make_float4(p2.x + bzs[cg+4], p2.y + bzs[cg+5],
                                p3.x + bzs[cg+6], p3.y + bzs[cg+7]);
        *(float4*)&g_fzs[base]     = v0;
        *(float4*)&g_fzs[base + 4] = v1;
    }
}

// ---------------- u = fx @ Ws[cat]; T = softplus(u . fz) -------------------
// Reads g_fxs contiguously (sorted). Writes g_us + g_T sorted.
#define FXP 36     // FxsT pitch (floats): k*36*4 bytes = 144 -> 16B-aligned rows
#define WSP 132
__global__ void u_kernel(const float* __restrict__ Ws){
    __shared__ __align__(16) float FxsT[128*FXP];   // [k][r]
    __shared__ __align__(16) float Wst [32*WSP];    // [k][c]
    int w = blockIdx.x;
    if (w >= g_nwork) return;
    int item  = g_work[w];
    int cat   = item >> 16, tile = item & 0xffff;
    int start = g_start[cat], cnt = g_cnt[cat];
    int i0    = tile * 32;
    int ni    = min(32, cnt - i0);
    int tid   = threadIdx.x;

    for (int e = tid; e < 32*ZD; e += 256){
        int r = e >> 7, k = e & 127;
        FxsT[k*FXP + r] = (r < ni) ? g_fxs[(size_t)(start + i0 + r)*ZD + k] : 0.f;
    }

    const float* Wc = Ws + (size_t)cat*ZD*ZD;
    int r0 = (tid >> 5) * 4;     // warp-uniform row group (0..28)
    int c0 = (tid & 31) * 4;     // lane col group (0..124)
    u64 acc2[4][2] = {};         // [col j][rowpair rp]: rp0=rows r0,r0+1; rp1=rows r0+2,r0+3

    for (int kt = 0; kt < ZD; kt += 32){
        __syncthreads();                       // FxsT visible (1st) / Wst reuse safe
        for (int e = tid; e < 32*128; e += 256){
            int k = e >> 7, cc = e & 127;
            Wst[k*WSP + cc] = Wc[(kt + k)*ZD + cc];
        }
        __syncthreads();
        #pragma unroll
        for (int k = 0; k < 32; k++){
            ulonglong2 av = *(const ulonglong2*)&FxsT[(kt+k)*FXP + r0];  // rows r0..r0+3 (broadcast)
            float4 bv = *(const float4*)&Wst[k*WSP + c0];
            u64 db0 = dup2(bv.x), db1 = dup2(bv.y), db2 = dup2(bv.z), db3 = dup2(bv.w);
            fma2(acc2[0][0], av.x, db0); fma2(acc2[0][1], av.y, db0);
            fma2(acc2[1][0], av.x, db1); fma2(acc2[1][1], av.y, db1);
            fma2(acc2[2][0], av.x, db2); fma2(acc2[2][1], av.y, db2);
            fma2(acc2[3][0], av.x, db3); fma2(acc2[3][1], av.y, db3);
        }
    }

    int lane = tid & 31;
    #pragma unroll
    for (int rp = 0; rp < 2; rp++){
        float2 u0 = unpk(acc2[0][rp]);
        float2 u1 = unpk(acc2[1][rp]);
        float2 u2 = unpk(acc2[2][rp]);
        float2 u3 = unpk(acc2[3][rp]);
        float rv[2][4] = {{u0.x, u1.x, u2.x, u3.x},   // row r0+2rp
                          {u0.y, u1.y, u2.y, u3.y}};  // row r0+2rp+1
        #pragma unroll
        for (int h = 0; h < 2; h++){
            int rr = r0 + 2*rp + h;            // warp-uniform
            float p = 0.f;
            if (rr < ni){
                size_t base = (size_t)(start + i0 + rr)*ZD + c0;
                *(float4*)&g_us[base] = make_float4(rv[h][0], rv[h][1], rv[h][2], rv[h][3]);
                const float4 fzr = *(const float4*)&g_fzs[base];
                p = rv[h][0]*fzr.x + rv[h][1]*fzr.y + rv[h][2]*fzr.z + rv[h][3]*fzr.w;
            }
            p += __shfl_xor_sync(0xffffffffu, p, 16);
            p += __shfl_xor_sync(0xffffffffu, p, 8);
            p += __shfl_xor_sync(0xffffffffu, p, 4);
            p += __shfl_xor_sync(0xffffffffu, p, 2);
            p += __shfl_xor_sync(0xffffffffu, p, 1);
            if (lane == 0 && rr < ni) g_T[start + i0 + rr] = softplusf(p);  // sorted order
        }
    }
}

// ---------------- neg_T + final output -------------------------------------
#define TP 132
__global__ void neg_kernel(float* __restrict__ out){
    __shared__ __align__(16) float Us[32*TP];
    __shared__ __align__(16) float Fs[32*TP];
    __shared__ int gidx[32];
    int w = blockIdx.x;
    if (w >= g_nwork) return;
    int item  = g_work[w];
    int cat   = item >> 16, tile = item & 0xffff;
    int start = g_start[cat], cnt = g_cnt[cat];
    int i0    = tile * 32;
    int ni    = min(32, cnt - i0);
    int tid   = threadIdx.x;

    if (tid < 32) gidx[tid] = (tid < ni) ? g_sorted[start + i0 + tid] : 0;
    for (int e = tid; e < 32*32; e += 256){
        int r = e >> 5, kq = e & 31;
        float4 v = make_float4(0.f,0.f,0.f,0.f);
        if (r < ni) v = *(const float4*)&g_us[(size_t)(start + i0 + r)*ZD + kq*4];
        *(float4*)&Us[r*TP + kq*4] = v;
    }

    int jj = tid & 31;           // j within tile = lane
    int ig = tid >> 5;           // warp owns rows ig*4..+3
    float sum[4] = {0.f, 0.f, 0.f, 0.f};

    for (int j0 = 0; j0 < cnt; j0 += 32){
        int nj = min(32, cnt - j0);
        __syncthreads();                       // Us/gidx visible (1st) / Fs reuse safe
        for (int e = tid; e < 32*32; e += 256){
            int r = e >> 5, kq = e & 31;
            float4 v = make_float4(0.f,0.f,0.f,0.f);
            if (r < nj) v = *(const float4*)&g_fzs[(size_t)(start + j0 + r)*ZD + kq*4];
            *(float4*)&Fs[r*TP + kq*4] = v;
        }
        __syncthreads();

        u64 acc2[4] = {};
        #pragma unroll
        for (int k0 = 0; k0 < ZD; k0 += 4){
            ulonglong2 f = *(const ulonglong2*)&Fs[jj*TP + k0];
            #pragma unroll
            for (int m = 0; m < 4; m++){
                ulonglong2 u = *(const ulonglong2*)&Us[(ig*4 + m)*TP + k0];  // broadcast
                fma2(acc2[m], u.x, f.x);
                fma2(acc2[m], u.y, f.y);
            }
        }
        #pragma unroll
        for (int m = 0; m < 4; m++){
            float2 s = unpk(acc2[m]);
            float v = (jj < nj) ? softplusf(s.x + s.y) : 0.f;
            v += __shfl_xor_sync(0xffffffffu, v, 16);
            v += __shfl_xor_sync(0xffffffffu, v, 8);
            v += __shfl_xor_sync(0xffffffffu, v, 4);
            v += __shfl_xor_sync(0xffffffffu, v, 2);
            v += __shfl_xor_sync(0xffffffffu, v, 1);
            sum[m] += v;
        }
    }

    if (jj == 0){
        float inv = 1.f / (float)cnt;
        #pragma unroll
        for (int m = 0; m < 4; m++){
            int rr = ig*4 + m;
            if (rr < ni){
                float tv = g_T[start + i0 + rr];          // sorted order
                out[gidx[rr]] = logf(tv + EPSV) - logf(sum[m]*inv + EPSV);
            }
        }
    }
}

// ---------------- launch ----------------------------------------------------
extern "C" void kernel_launch(void* const* d_in, const int* in_sizes, int n_in,
                              void* d_out, int out_size){
    const float* x  = (const float*)d_in[0];
    const int*   c  = (const int*)  d_in[1];
    const float* z  = (const float*)d_in[2];
    const float* W1 = (const float*)d_in[3];
    const float* b1 = (const float*)d_in[4];
    const float* W2 = (const float*)d_in[5];
    const float* b2 = (const float*)d_in[6];
    const float* Wz = (const float*)d_in[7];
    const float* bz = (const float*)d_in[8];
    const float* Ws = (const float*)d_in[9];
    float* out = (float*)d_out;

    bucket_kernel <<<1, 1024>>>(c);
    fx_kernel     <<<NN/32, 256>>>(x, W1, b1, W2, b2);
    fz_kernel     <<<NN/32, 256>>>(z, Wz, bz);
    u_kernel      <<<NWORK_MAX, 256>>>(Ws);
    neg_kernel    <<<NWORK_MAX, 256>>>(out);
}

// round 8
// speedup vs baseline: 1.3968x; 1.3968x over previous
#include <cuda_runtime.h>

#define NN 8192
#define INDIM 512
#define HID 50
#define ZD 128
#define NCAT 64
#define EPSV 1e-8f
#define NWORK_MAX (NN/32 + NCAT)

typedef unsigned long long u64;

// ---------------- scratch (device globals; no allocation allowed) ----------
__device__ float g_fxs[NN*ZD];   // fx in sorted order
__device__ float g_fzs[NN*ZD];   // fz in sorted order
__device__ int   g_cnt[NCAT], g_start[NCAT];
__device__ int   g_sorted[NN];   // sorted pos -> original idx
__device__ int   g_pos[NN];      // original idx -> sorted pos
__device__ int   g_work[NWORK_MAX];
__device__ int   g_nwork;

// ---------------- f32x2 helpers ---------------------------------------------
__device__ __forceinline__ u64 dup2(float x){
    u64 r; asm("mov.b64 %0, {%1, %1};" : "=l"(r) : "f"(x)); return r;
}
__device__ __forceinline__ void fma2(u64 &d, u64 a, u64 b){
    asm("fma.rn.f32x2 %0, %1, %2, %0;" : "+l"(d) : "l"(a), "l"(b));
}
__device__ __forceinline__ float2 unpk(u64 v){
    float2 f; asm("mov.b64 {%0, %1}, %2;" : "=f"(f.x), "=f"(f.y) : "l"(v)); return f;
}
__device__ __forceinline__ float softplusf(float v){
    // __expf: ~2ulp RELATIVE error (safe); log1pf accurate for tiny args.
    return fmaxf(v, 0.f) + log1pf(__expf(-fabsf(v)));
}

// ---------------- fused bucket sort (single block) --------------------------
__global__ void bucket_kernel(const int* __restrict__ c){
    __shared__ int s_cnt[NCAT];
    __shared__ int s_cursor[NCAT];
    __shared__ int s_cat[NN];
    int tid = threadIdx.x;

    if (tid < NCAT) s_cnt[tid] = 0;
    __syncthreads();
    for (int i = tid; i < NN; i += 1024){
        int cc = c[i];
        cc = min(max(cc, 0), NCAT - 1);
        s_cat[i] = cc;
        atomicAdd(&s_cnt[cc], 1);
    }
    __syncthreads();
    if (tid == 0){
        int s = 0, w = 0;
        for (int cc = 0; cc < NCAT; cc++){
            s_cursor[cc] = s;
            g_start[cc]  = s;
            int n = s_cnt[cc];
            g_cnt[cc] = n;
            s += n;
            int nt = (n + 31) >> 5;
            for (int t = 0; t < nt; t++) g_work[w++] = (cc << 16) | t;
        }
        g_nwork = w;
    }
    __syncthreads();
    for (int i = tid; i < NN; i += 1024){
        int p = atomicAdd(&s_cursor[s_cat[i]], 1);
        g_sorted[p] = i;
        g_pos[i]    = p;
    }
}

// ---------------- fx = relu(x@W1+b1)@W2+b2  (32 rows / block, pipelined) ----
// phase1: As = sbuf[0..1152) pitch36, Bs = sbuf[1152..3200) pitch64
// phase2: Hs = sbuf[0..1664) pitch52, W2s = sbuf[1664..8064) pitch128
__global__ void fx_kernel(const float* __restrict__ x,  const float* __restrict__ W1,
                          const float* __restrict__ b1, const float* __restrict__ W2,
                          const float* __restrict__ b2){
    __shared__ __align__(16) float sbuf[8064];
    __shared__ float b1s[64];
    __shared__ float b2s[128];
    __shared__ int   posS[32];
    float* As  = sbuf;            // [32][36]
    float* Bs  = sbuf + 1152;     // [32][64]
    float* Hs  = sbuf;            // [32][52]
    float* W2s = sbuf + 1664;     // [50][128]

    int tid  = threadIdx.x;
    int row0 = blockIdx.x * 32;
    if (tid < 64)  b1s[tid] = (tid < HID) ? b1[tid] : 0.f;
    if (tid < 128) b2s[tid] = b2[tid];
    if (tid < 32)  posS[tid] = g_pos[row0 + tid];

    // preload W2 into registers (stored to smem after GEMM1)
    float4 w2r[7];
    #pragma unroll
    for (int i = 0; i < 7; i++){
        int q = tid + 256*i;                 // 1600 float4 slots
        if (q < 1600) w2r[i] = *(const float4*)&W2[q*4];
    }

    // GEMM1 prefetch regs
    int ar = tid >> 3, ac4 = tid & 7;        // A: 32x32 -> 256 float4
    float4 pa = *(const float4*)&x[(size_t)(row0 + ar)*INDIM + ac4*4];
    float pb[8];
    #pragma unroll
    for (int i = 0; i < 8; i++){
        int e = tid + 256*i;                 // B: 32x64 slots
        int k = e >> 6, j = e & 63;
        pb[i] = (j < HID) ? W1[(size_t)k*HID + j] : 0.f;
    }

    int rg = (tid >> 4) * 2;     // 0..30
    int cg = (tid & 15) * 4;     // 0..60
    u64 acc2[2][2] = {};

    for (int t = 0; t < 16; t++){
        __syncthreads();
        *(float4*)&As[ar*36 + ac4*4] = pa;
        #pragma unroll
        for (int i = 0; i < 8; i++){
            int e = tid + 256*i;
            Bs[(e >> 6)*64 + (e & 63)] = pb[i];
        }
        __syncthreads();
        if (t < 15){
            int k0 = (t+1)*32;
            pa = *(const float4*)&x[(size_t)(row0 + ar)*INDIM + k0 + ac4*4];
            #pragma unroll
            for (int i = 0; i < 8; i++){
                int e = tid + 256*i;
                int k = e >> 6, j = e & 63;
                pb[i] = (j < HID) ? W1[(size_t)(k0 + k)*HID + j] : 0.f;
            }
        }
        #pragma unroll
        for (int k = 0; k < 32; k++){
            u64 da0 = dup2(As[rg*36 + k]);
            u64 da1 = dup2(As[(rg+1)*36 + k]);
            ulonglong2 bb = *(const ulonglong2*)&Bs[k*64 + cg];
            fma2(acc2[0][0], da0, bb.x); fma2(acc2[0][1], da0, bb.y);
            fma2(acc2[1][0], da1, bb.x); fma2(acc2[1][1], da1, bb.y);
        }
    }
    __syncthreads();

    // hidden (ReLU) + stage W2 (As/Bs dead)
    #pragma unroll
    for (int i = 0; i < 2; i++){
        float2 p0 = unpk(acc2[i][0]);
        float2 p1 = unpk(acc2[i][1]);
        float hv[4] = {p0.x, p0.y, p1.x, p1.y};
        #pragma unroll
        for (int j = 0; j < 4; j++){
            int cc = cg + j;
            if (cc < HID) Hs[(rg+i)*52 + cc] = fmaxf(hv[j] + b1s[cc], 0.f);
        }
    }
    #pragma unroll
    for (int i = 0; i < 7; i++){
        int q = tid + 256*i;
        if (q < 1600) *(float4*)&W2s[q*4] = w2r[i];
    }
    __syncthreads();

    // GEMM2: 32x128, thread tile 4 rows x 4 cols
    {
        int r0 = (tid >> 5) * 4;
        int c0 = (tid & 31) * 4;
        u64 a2[4][2] = {};
        #pragma unroll
        for (int k = 0; k < HID; k++){
            ulonglong2 bb = *(const ulonglong2*)&W2s[k*128 + c0];
            #pragma unroll
            for (int i = 0; i < 4; i++){
                u64 da = dup2(Hs[(r0+i)*52 + k]);
                fma2(a2[i][0], da, bb.x);
                fma2(a2[i][1], da, bb.y);
            }
        }
        #pragma unroll
        for (int i = 0; i < 4; i++){
            float2 p0 = unpk(a2[i][0]);
            float2 p1 = unpk(a2[i][1]);
            float4 v = make_float4(p0.x + b2s[c0], p0.y + b2s[c0+1],
                                   p1.x + b2s[c0+2], p1.y + b2s[c0+3]);
            *(float4*)&g_fxs[(size_t)posS[r0+i]*ZD + c0] = v;
        }
    }
}

// ---------------- fz = z@Wz+bz  (32 rows / block, pipelined) ---------------
__global__ void fz_kernel(const float* __restrict__ z, const float* __restrict__ Wz,
                          const float* __restrict__ bz){
    __shared__ __align__(16) float Zs[32*36];
    __shared__ __align__(16) float Wzt[32*132];
    __shared__ float bzs[128];
    __shared__ int   posS[32];
    int tid  = threadIdx.x;
    int row0 = blockIdx.x * 32;
    if (tid < 128) bzs[tid] = bz[tid];
    if (tid < 32)  posS[tid] = g_pos[row0 + tid];

    int ar = tid >> 3, ac4 = tid & 7;
    float4 pz = *(const float4*)&z[(size_t)(row0 + ar)*ZD + ac4*4];
    float4 pw[4];
    #pragma unroll
    for (int i = 0; i < 4; i++){
        int q = tid + 256*i;                 // 1024 float4 slots (32x128)
        pw[i] = *(const float4*)&Wz[(size_t)(q >> 5)*ZD + (q & 31)*4];
    }

    int rg = (tid >> 4) * 2;     // 0..30
    int cg = (tid & 15) * 4;     // two col groups: cg..cg+3 and cg+64..cg+67
    u64 acc2[2][4] = {};

    for (int kt = 0; kt < 4; kt++){
        __syncthreads();
        *(float4*)&Zs[ar*36 + ac4*4] = pz;
        #pragma unroll
        for (int i = 0; i < 4; i++){
            int q = tid + 256*i;
            *(float4*)&Wzt[(q >> 5)*132 + (q & 31)*4] = pw[i];
        }
        __syncthreads();
        if (kt < 3){
            int k0 = (kt+1)*32;
            pz = *(const float4*)&z[(size_t)(row0 + ar)*ZD + k0 + ac4*4];
            #pragma unroll
            for (int i = 0; i < 4; i++){
                int q = tid + 256*i;
                pw[i] = *(const float4*)&Wz[(size_t)(k0 + (q >> 5))*ZD + (q & 31)*4];
            }
        }
        #pragma unroll
        for (int k = 0; k < 32; k++){
            u64 da0 = dup2(Zs[rg*36 + k]);
            u64 da1 = dup2(Zs[(rg+1)*36 + k]);
            ulonglong2 b0 = *(const ulonglong2*)&Wzt[k*132 + cg];
            ulonglong2 b1 = *(const ulonglong2*)&Wzt[k*132 + cg + 64];
            fma2(acc2[0][0], da0, b0.x); fma2(acc2[0][1], da0, b0.y);
            fma2(acc2[0][2], da0, b1.x); fma2(acc2[0][3], da0, b1.y);
            fma2(acc2[1][0], da1, b0.x); fma2(acc2[1][1], da1, b0.y);
            fma2(acc2[1][2], da1, b1.x); fma2(acc2[1][3], da1, b1.y);
        }
    }

    #pragma unroll
    for (int i = 0; i < 2; i++){
        size_t base = (size_t)posS[rg+i]*ZD;
        float2 p0 = unpk(acc2[i][0]), p1 = unpk(acc2[i][1]);
        float2 p2 = unpk(acc2[i][2]), p3 = unpk(acc2[i][3]);
        *(float4*)&g_fzs[base + cg] =
            make_float4(p0.x + bzs[cg],   p0.y + bzs[cg+1],
                        p1.x + bzs[cg+2], p1.y + bzs[cg+3]);
        *(float4*)&g_fzs[base + cg + 64] =
            make_float4(p2.x + bzs[cg+64], p2.y + bzs[cg+65],
                        p3.x + bzs[cg+66], p3.y + bzs[cg+67]);
    }
}

// ---------------- fused u + neg + output ------------------------------------
// block = (cat, 32-row itile). Phase1: U = Fx@Ws[cat] -> smem. Phase2: neg loop.
// phase1: FxsT = sbuf[0..4608) pitch36 [k][r]; Wst = sbuf[4608..8832) pitch132
// phase2: Us = sbuf[0..4224) pitch132;  Fs = sbuf[4224..8448) pitch132
__global__ void uneg_kernel(const float* __restrict__ Ws, float* __restrict__ out){
    __shared__ __align__(16) float sbuf[8832];
    __shared__ float Ts[32];
    __shared__ int   gidx[32];
    float* FxsT = sbuf;
    float* Wst  = sbuf + 4608;
    float* Us   = sbuf;
    float* Fs   = sbuf + 4224;

    int w = blockIdx.x;
    if (w >= g_nwork) return;
    int item  = g_work[w];
    int cat   = item >> 16, tile = item & 0xffff;
    int start = g_start[cat], cnt = g_cnt[cat];
    int i0    = tile * 32;
    int ni    = min(32, cnt - i0);
    int tid   = threadIdx.x;

    if (tid < 32) gidx[tid] = (tid < ni) ? g_sorted[start + i0 + tid] : 0;

    // stage fx tile transposed: thread = (kw=tid>>5, r=tid&31), 4 float4 each
    {
        int r = tid & 31;
        #pragma unroll
        for (int i = 0; i < 4; i++){
            int k4 = (tid >> 5) + 8*i;       // 0..31
            float4 v = make_float4(0.f,0.f,0.f,0.f);
            if (r < ni) v = *(const float4*)&g_fxs[(size_t)(start + i0 + r)*ZD + k4*4];
            FxsT[(k4*4+0)*36 + r] = v.x;
            FxsT[(k4*4+1)*36 + r] = v.y;
            FxsT[(k4*4+2)*36 + r] = v.z;
            FxsT[(k4*4+3)*36 + r] = v.w;
        }
    }

    const float* Wc = Ws + (size_t)cat*ZD*ZD;
    float4 pw[4];
    #pragma unroll
    for (int i = 0; i < 4; i++){
        int q = tid + 256*i;                 // 1024 slots (32x128)
        pw[i] = *(const float4*)&Wc[(size_t)(q >> 5)*ZD + (q & 31)*4];
    }
    // early prefetch of first Fs tile (held through phase 1)
    float4 pf[4];
    {
        int nj0 = min(32, cnt);
        #pragma unroll
        for (int i = 0; i < 4; i++){
            int q = tid + 256*i;
            int r = q >> 5;
            pf[i] = make_float4(0.f,0.f,0.f,0.f);
            if (r < nj0) pf[i] = *(const float4*)&g_fzs[(size_t)(start + r)*ZD + (q & 31)*4];
        }
    }

    int r0 = (tid >> 5) * 4;     // warp-uniform row group
    int c0 = (tid & 31) * 4;     // lane col group
    u64 acc2[4][2] = {};         // [col j][rowpair]

    for (int kt = 0; kt < ZD; kt += 32){
        __syncthreads();                     // FxsT staged (1st) / Wst consumers done
        #pragma unroll
        for (int i = 0; i < 4; i++){
            int q = tid + 256*i;
            *(float4*)&Wst[(q >> 5)*132 + (q & 31)*4] = pw[i];
        }
        __syncthreads();
        if (kt < ZD - 32){
            #pragma unroll
            for (int i = 0; i < 4; i++){
                int q = tid + 256*i;
                pw[i] = *(const float4*)&Wc[(size_t)(kt + 32 + (q >> 5))*ZD + (q & 31)*4];
            }
        }
        #pragma unroll
        for (int k = 0; k < 32; k++){
            ulonglong2 av = *(const ulonglong2*)&FxsT[(kt+k)*36 + r0];  // broadcast
            float4 bv = *(const float4*)&Wst[k*132 + c0];
            u64 d0 = dup2(bv.x), d1 = dup2(bv.y), d2 = dup2(bv.z), d3 = dup2(bv.w);
            fma2(acc2[0][0], av.x, d0); fma2(acc2[0][1], av.y, d0);
            fma2(acc2[1][0], av.x, d1); fma2(acc2[1][1], av.y, d1);
            fma2(acc2[2][0], av.x, d2); fma2(acc2[2][1], av.y, d2);
            fma2(acc2[3][0], av.x, d3); fma2(acc2[3][1], av.y, d3);
        }
    }
    __syncthreads();                         // phase-1 reads done; safe to overwrite

    // write U tile to smem (rows beyond ni hold zeros)
    {
        float2 q00 = unpk(acc2[0][0]), q10 = unpk(acc2[1][0]),
               q20 = unpk(acc2[2][0]), q30 = unpk(acc2[3][0]);
        float2 q01 = unpk(acc2[0][1]), q11 = unpk(acc2[1][1]),
               q21 = unpk(acc2[2][1]), q31 = unpk(acc2[3][1]);
        *(float4*)&Us[(r0+0)*132 + c0] = make_float4(q00.x, q10.x, q20.x, q30.x);
        *(float4*)&Us[(r0+1)*132 + c0] = make_float4(q00.y, q10.y, q20.y, q30.y);
        *(float4*)&Us[(r0+2)*132 + c0] = make_float4(q01.x, q11.x, q21.x, q31.x);
        *(float4*)&Us[(r0+3)*132 + c0] = make_float4(q01.y, q11.y, q21.y, q31.y);
    }

    // phase 2: neg loop over all j-tiles of this category
    int jj = tid & 31;
    int ig = tid >> 5;
    float sum[4] = {0.f, 0.f, 0.f, 0.f};

    for (int j0 = 0; j0 < cnt; j0 += 32){
        int nj = min(32, cnt - j0);
        __syncthreads();                     // Us visible (1st) / Fs consumers done
        #pragma unroll
        for (int i = 0; i < 4; i++){
            int q = tid + 256*i;
            *(float4*)&Fs[(q >> 5)*132 + (q & 31)*4] = pf[i];
        }
        __syncthreads();
        if (j0 + 32 < cnt){
            int njn = min(32, cnt - j0 - 32);
            #pragma unroll
            for (int i = 0; i < 4; i++){
                int q = tid + 256*i;
                int r = q >> 5;
                pf[i] = make_float4(0.f,0.f,0.f,0.f);
                if (r < njn) pf[i] = *(const float4*)&g_fzs[(size_t)(start + j0 + 32 + r)*ZD + (q & 31)*4];
            }
        }

        u64 a4[4] = {};
        #pragma unroll
        for (int k0 = 0; k0 < ZD; k0 += 4){
            ulonglong2 f = *(const ulonglong2*)&Fs[jj*132 + k0];
            #pragma unroll
            for (int m = 0; m < 4; m++){
                ulonglong2 u = *(const ulonglong2*)&Us[(ig*4 + m)*132 + k0]; // broadcast
                fma2(a4[m], u.x, f.x);
                fma2(a4[m], u.y, f.y);
            }
        }
        #pragma unroll
        for (int m = 0; m < 4; m++){
            float2 s = unpk(a4[m]);
            float d = s.x + s.y;
            int rr = ig*4 + m;
            if (j0 == i0 && jj == rr && rr < ni) Ts[rr] = softplusf(d);  // diagonal = T
            float v = (jj < nj) ? softplusf(d) : 0.f;
            v += __shfl_xor_sync(0xffffffffu, v, 16);
            v += __shfl_xor_sync(0xffffffffu, v, 8);
            v += __shfl_xor_sync(0xffffffffu, v, 4);
            v += __shfl_xor_sync(0xffffffffu, v, 2);
            v += __shfl_xor_sync(0xffffffffu, v, 1);
            sum[m] += v;
        }
    }
    __syncthreads();                         // Ts visible

    if (jj == 0){
        float inv = 1.f / (float)cnt;
        #pragma unroll
        for (int m = 0; m < 4; m++){
            int rr = ig*4 + m;
            if (rr < ni)
                out[gidx[rr]] = logf(Ts[rr] + EPSV) - logf(sum[m]*inv + EPSV);
        }
    }
}

// ---------------- launch ----------------------------------------------------
extern "C" void kernel_launch(void* const* d_in, const int* in_sizes, int n_in,
                              void* d_out, int out_size){
    const float* x  = (const float*)d_in[0];
    const int*   c  = (const int*)  d_in[1];
    const float* z  = (const float*)d_in[2];
    const float* W1 = (const float*)d_in[3];
    const float* b1 = (const float*)d_in[4];
    const float* W2 = (const float*)d_in[5];
    const float* b2 = (const float*)d_in[6];
    const float* Wz = (const float*)d_in[7];
    const float* bz = (const float*)d_in[8];
    const float* Ws = (const float*)d_in[9];
    float* out = (float*)d_out;

    bucket_kernel <<<1, 1024>>>(c);
    fx_kernel     <<<NN/32, 256>>>(x, W1, b1, W2, b2);
    fz_kernel     <<<NN/32, 256>>>(z, Wz, bz);
    uneg_kernel   <<<NWORK_MAX, 256>>>(Ws, out);
}